// round 7
// baseline (speedup 1.0000x reference)
#include <cuda_runtime.h>

typedef unsigned long long ull;

// ---------------- problem constants ----------------
#define NDST0 67584
#define NDST1 6144
#define NDST2 1024
#define NE0   1013760
#define NE1   61440
#define NE2   5120
#define FIN   128
#define FH    256
#define NCLS  47

// ---------------- device scratch (referenced ONLY from device code) ----------------
__device__ float4 g_agg0 [NDST0 * FIN / 4];   // mean-aggregated neighbors, layer 0
__device__ float4 g_h1   [NDST0 * FH  / 4];   // layer-0 output (feeds layer-1 self+neigh)
__device__ float4 g_agg1 [NDST1 * FH  / 4];
__device__ float4 g_h2   [NDST1 * FH  / 4];   // layer-1 output
__device__ float4 g_agg2 [NDST2 * FH  / 4];
__device__ int    g_deg  [NDST0];
__device__ int    g_cur  [NDST0];
__device__ int    g_off  [NDST0 + 1];
__device__ int    g_esrc [NE0];               // CSR-ordered source row ids

// ---------------- f32x2 packed-FMA helpers (Blackwell FFMA2) ----------------
__device__ __forceinline__ void ffma2(ull& d, ull a, ull b)
{
    asm("fma.rn.f32x2 %0, %1, %2, %0;" : "+l"(d) : "l"(a), "l"(b));
}
__device__ __forceinline__ ull pack_dup(float v)
{
    ull r;
    asm("mov.b64 %0, {%1, %1};" : "=l"(r) : "f"(v));
    return r;
}
__device__ __forceinline__ void unpack2(float& lo, float& hi, ull p)
{
    asm("mov.b64 {%0, %1}, %2;" : "=f"(lo), "=f"(hi) : "l"(p));
}

// ---------------- tiny utility kernels ----------------
__global__ void zero2_kernel(int n)
{
    int i = blockIdx.x * blockDim.x + threadIdx.x;
    if (i < n) { g_deg[i] = 0; g_cur[i] = 0; }
}

__global__ void hist_kernel(const int* __restrict__ dst, int E)
{
    int e = blockIdx.x * blockDim.x + threadIdx.x;
    if (e < E) atomicAdd(&g_deg[dst[e]], 1);
}

// single-block exclusive scan over g_deg -> g_off (shfl-based)
__global__ void scan_kernel(int n)
{
    __shared__ int warpsum[32];
    __shared__ int s_carry;
    const int tid  = threadIdx.x;
    const int lane = tid & 31;
    const int wid  = tid >> 5;
    if (tid == 0) s_carry = 0;
    __syncthreads();
    for (int base = 0; base < n; base += 1024) {
        int idx = base + tid;
        int v = (idx < n) ? g_deg[idx] : 0;
        int x = v;
#pragma unroll
        for (int st = 1; st < 32; st <<= 1) {
            int t = __shfl_up_sync(0xFFFFFFFFu, x, st);
            if (lane >= st) x += t;
        }
        if (lane == 31) warpsum[wid] = x;
        __syncthreads();
        if (wid == 0) {
            int w = warpsum[lane];
#pragma unroll
            for (int st = 1; st < 32; st <<= 1) {
                int t = __shfl_up_sync(0xFFFFFFFFu, w, st);
                if (lane >= st) w += t;
            }
            warpsum[lane] = w;   // inclusive warp totals
        }
        __syncthreads();
        int woff  = (wid > 0) ? warpsum[wid - 1] : 0;
        int carry = s_carry;
        if (idx < n) g_off[idx] = carry + woff + x - v;   // exclusive
        __syncthreads();
        if (tid == 0) s_carry = carry + warpsum[31];
        __syncthreads();
    }
    if (threadIdx.x == 0) g_off[n] = s_carry;
}

// CSR scatter; REMAP=1 resolves the emb-table indirection (layer 0)
template <int REMAP>
__global__ void scatter_kernel(const int* __restrict__ src, const int* __restrict__ dst, int E,
                               const int* __restrict__ remap)
{
    int e = blockIdx.x * blockDim.x + threadIdx.x;
    if (e >= E) return;
    int d = dst[e];
    int p = g_off[d] + atomicAdd(&g_cur[d], 1);
    int s = src[e];
    g_esrc[p] = REMAP ? remap[s] : s;
}

// ---------------- mean aggregation: one warp per destination ----------------
template <int LAYER>
__global__ void agg_kernel(const float4* __restrict__ hExt, int n_dst)
{
    const float4* __restrict__ h4 =
        (LAYER == 0) ? hExt : (LAYER == 1) ? (const float4*)g_h1 : (const float4*)g_h2;
    float4* __restrict__ agg4 =
        (LAYER == 0) ? g_agg0 : (LAYER == 1) ? g_agg1 : g_agg2;
    const int VPL = (LAYER == 0) ? 1 : 2;
    const int F4  = VPL * 32;

    int w = (blockIdx.x * blockDim.x + threadIdx.x) >> 5;
    int lane = threadIdx.x & 31;
    if (w >= n_dst) return;
    int s = g_off[w], e = g_off[w + 1];

    float4 acc[VPL];
#pragma unroll
    for (int v = 0; v < VPL; v++) acc[v] = make_float4(0.f, 0.f, 0.f, 0.f);

    int i = s;
    for (; i + 1 < e; i += 2) {           // unroll x2 for MLP
        int r0 = g_esrc[i], r1 = g_esrc[i + 1];
#pragma unroll
        for (int v = 0; v < VPL; v++) {
            float4 x = h4[(size_t)r0 * F4 + v * 32 + lane];
            float4 y = h4[(size_t)r1 * F4 + v * 32 + lane];
            acc[v].x += x.x + y.x; acc[v].y += x.y + y.y;
            acc[v].z += x.z + y.z; acc[v].w += x.w + y.w;
        }
    }
    if (i < e) {
        int r0 = g_esrc[i];
#pragma unroll
        for (int v = 0; v < VPL; v++) {
            float4 x = h4[(size_t)r0 * F4 + v * 32 + lane];
            acc[v].x += x.x; acc[v].y += x.y; acc[v].z += x.z; acc[v].w += x.w;
        }
    }
    int cnt = e - s;
    float inv = 1.0f / (float)(cnt > 0 ? cnt : 1);
#pragma unroll
    for (int v = 0; v < VPL; v++) {
        agg4[(size_t)w * F4 + v * 32 + lane] =
            make_float4(acc[v].x * inv, acc[v].y * inv, acc[v].z * inv, acc[v].w * inv);
    }
}

// ---------------- dual-operand SGEMM with packed FFMA2 ----------------
// C = relu( A1@B1 + A2@B2 + bias )
// LAYER 0: A1 = emb with row remap via input_nodes, A2 = g_agg0, C = g_h1, K=FIN
// LAYER 1: A1 = g_h1,                               A2 = g_agg1, C = g_h2, K=FH
// BM=BN=128, BK=8, 256 threads, 8x8 per thread (accumulated as 8x4 f32x2 pairs)
template <int LAYER>
__global__ void __launch_bounds__(256, 2) gemm2_kernel(
    const float* __restrict__ A1ext,         // emb (layer 0); unused layer 1
    const int*   __restrict__ inodes,        // input_nodes (layer 0); unused layer 1
    const float* __restrict__ B1, const float* __restrict__ B2,
    const float* __restrict__ bias)
{
    const float* __restrict__ A1 =
        (LAYER == 0) ? A1ext : (const float*)g_h1;
    const float* __restrict__ A2 =
        (LAYER == 0) ? (const float*)g_agg0 : (const float*)g_agg1;
    float* __restrict__ C = (LAYER == 0) ? (float*)g_h1 : (float*)g_h2;
    const int K = (LAYER == 0) ? FIN : FH;
    const int N = FH;

    __shared__ float As[8][128];   // transposed A tile (k-major)
    __shared__ float Bs[8][128];
    const int tid = threadIdx.x;
    const int tx = tid & 15;       // N direction (16)
    const int ty = tid >> 4;       // M direction (16)
    const int bx = blockIdx.x;
    const int by = blockIdx.y;

    const int aRow = tid >> 1;             // 0..127
    const int aCol = (tid & 1) << 2;       // 0 or 4
    const int bRow = tid >> 5;             // 0..7
    const int bCol = (tid & 31) << 2;      // 0..124

    const int am   = by * 128 + aRow;                        // logical A row
    const int amA1 = (LAYER == 0) ? __ldg(&inodes[am]) : am; // physical row for A1 phase

    ull acc2[8][4];                // [row i][col pair jp]; pair = cols {2jp, 2jp+1} of the 8
#pragma unroll
    for (int i = 0; i < 8; i++)
#pragma unroll
        for (int jp = 0; jp < 4; jp++) acc2[i][jp] = 0ull;

    const int KT = K >> 3;
    for (int t = 0; t < 2 * KT; t++) {
        const bool ph1 = (t < KT);
        const float* A = ph1 ? A1 : A2;
        const float* B = ph1 ? B1 : B2;
        const int arow = ph1 ? amA1 : am;
        const int k0 = (ph1 ? t : t - KT) << 3;

        float4 av = *(const float4*)(A + (size_t)arow * K + k0 + aCol);
        float4 bv = *(const float4*)(B + (size_t)(k0 + bRow) * N + bx * 128 + bCol);
        As[aCol + 0][aRow] = av.x; As[aCol + 1][aRow] = av.y;
        As[aCol + 2][aRow] = av.z; As[aCol + 3][aRow] = av.w;
        *(float4*)&Bs[bRow][bCol] = bv;
        __syncthreads();

#pragma unroll
        for (int k = 0; k < 8; k++) {
            float4 a0 = *(const float4*)&As[k][ty * 4];
            float4 a1 = *(const float4*)&As[k][64 + ty * 4];
            // B pairs read directly as packed f32x2 (memory layout == register layout)
            const ull* bp0 = (const ull*)&Bs[k][tx * 4];
            const ull* bp1 = (const ull*)&Bs[k][64 + tx * 4];
            ull b2[4] = { bp0[0], bp0[1], bp1[0], bp1[1] };
            float af[8] = {a0.x, a0.y, a0.z, a0.w, a1.x, a1.y, a1.z, a1.w};
#pragma unroll
            for (int i = 0; i < 8; i++) {
                ull a2 = pack_dup(af[i]);
#pragma unroll
                for (int jp = 0; jp < 4; jp++) ffma2(acc2[i][jp], a2, b2[jp]);
            }
        }
        __syncthreads();
    }

    const int c0 = bx * 128 + tx * 4;
    const int c1 = bx * 128 + 64 + tx * 4;
    float4 bias0 = *(const float4*)(bias + c0);
    float4 bias1 = *(const float4*)(bias + c1);
#pragma unroll
    for (int i = 0; i < 8; i++) {
        int r = by * 128 + ((i < 4) ? (ty * 4 + i) : (64 + ty * 4 + i - 4));
        float c8[8];
#pragma unroll
        for (int jp = 0; jp < 4; jp++) unpack2(c8[2 * jp], c8[2 * jp + 1], acc2[i][jp]);
        float4 v0 = make_float4(c8[0] + bias0.x, c8[1] + bias0.y,
                                c8[2] + bias0.z, c8[3] + bias0.w);
        float4 v1 = make_float4(c8[4] + bias1.x, c8[5] + bias1.y,
                                c8[6] + bias1.z, c8[7] + bias1.w);
        v0.x = fmaxf(v0.x, 0.f); v0.y = fmaxf(v0.y, 0.f);
        v0.z = fmaxf(v0.z, 0.f); v0.w = fmaxf(v0.w, 0.f);
        v1.x = fmaxf(v1.x, 0.f); v1.y = fmaxf(v1.y, 0.f);
        v1.z = fmaxf(v1.z, 0.f); v1.w = fmaxf(v1.w, 0.f);
        *(float4*)(C + (size_t)r * N + c0) = v0;
        *(float4*)(C + (size_t)r * N + c1) = v1;
    }
}

// ---------------- layer 2 (tiny, N=47) ----------------
__global__ void layer2_kernel(const float* __restrict__ Ws, const float* __restrict__ Wn,
                              const float* __restrict__ b, float* __restrict__ out)
{
    int m = blockIdx.x;
    int n = threadIdx.x;
    if (n >= NCLS) return;
    float acc = b[n];
    const float* hr = (const float*)g_h2   + (size_t)m * FH;
    const float* ar = (const float*)g_agg2 + (size_t)m * FH;
#pragma unroll 4
    for (int k = 0; k < FH; k++)
        acc += hr[k] * Ws[k * NCLS + n] + ar[k] * Wn[k * NCLS + n];
    out[m * NCLS + n] = acc;
}

// ---------------- orchestration (kernel launches ONLY — graph-capturable) ----------------
extern "C" void kernel_launch(void* const* d_in, const int* in_sizes, int n_in,
                              void* d_out, int out_size)
{
    (void)in_sizes; (void)n_in; (void)out_size;
    // metadata.txt order == setup_inputs() insertion order:
    // emb_table, input_nodes, src0, dst0, src1, dst1, src2, dst2,
    // Wself0, Wneigh0, b0, Wself1, Wneigh1, b1, Wself2, Wneigh2, b2
    const float* emb         = (const float*)d_in[0];
    const int*   input_nodes = (const int*)  d_in[1];
    const int*   src0        = (const int*)  d_in[2];
    const int*   dst0        = (const int*)  d_in[3];
    const int*   src1        = (const int*)  d_in[4];
    const int*   dst1        = (const int*)  d_in[5];
    const int*   src2        = (const int*)  d_in[6];
    const int*   dst2        = (const int*)  d_in[7];
    const float* Ws0         = (const float*)d_in[8];
    const float* Wn0         = (const float*)d_in[9];
    const float* b0          = (const float*)d_in[10];
    const float* Ws1         = (const float*)d_in[11];
    const float* Wn1         = (const float*)d_in[12];
    const float* b1          = (const float*)d_in[13];
    const float* Ws2         = (const float*)d_in[14];
    const float* Wn2         = (const float*)d_in[15];
    const float* b2          = (const float*)d_in[16];
    float* out = (float*)d_out;

    const int TB = 256;

    // ---- layer 0 ----
    zero2_kernel<<<(NDST0 + TB - 1) / TB, TB>>>(NDST0);
    hist_kernel<<<(NE0 + TB - 1) / TB, TB>>>(dst0, NE0);
    scan_kernel<<<1, 1024>>>(NDST0);
    scatter_kernel<1><<<(NE0 + TB - 1) / TB, TB>>>(src0, dst0, NE0, input_nodes);
    agg_kernel<0><<<(NDST0 + 7) / 8, TB>>>((const float4*)emb, NDST0);
    {
        dim3 grid(FH / 128, NDST0 / 128);
        gemm2_kernel<0><<<grid, 256>>>(emb, input_nodes, Ws0, Wn0, b0);
    }

    // ---- layer 1 ----
    zero2_kernel<<<(NDST1 + TB - 1) / TB, TB>>>(NDST1);
    hist_kernel<<<(NE1 + TB - 1) / TB, TB>>>(dst1, NE1);
    scan_kernel<<<1, 1024>>>(NDST1);
    scatter_kernel<0><<<(NE1 + TB - 1) / TB, TB>>>(src1, dst1, NE1, input_nodes);
    agg_kernel<1><<<(NDST1 + 7) / 8, TB>>>((const float4*)emb, NDST1);
    {
        dim3 grid(FH / 128, NDST1 / 128);
        gemm2_kernel<1><<<grid, 256>>>(emb, input_nodes, Ws1, Wn1, b1);
    }

    // ---- layer 2 ----
    zero2_kernel<<<(NDST2 + TB - 1) / TB, TB>>>(NDST2);
    hist_kernel<<<(NE2 + TB - 1) / TB, TB>>>(dst2, NE2);
    scan_kernel<<<1, 1024>>>(NDST2);
    scatter_kernel<0><<<(NE2 + TB - 1) / TB, TB>>>(src2, dst2, NE2, input_nodes);
    agg_kernel<2><<<(NDST2 + 7) / 8, TB>>>((const float4*)emb, NDST2);
    layer2_kernel<<<NDST2, 64>>>(Ws2, Wn2, b2, out);
}

// round 12
// speedup vs baseline: 1.4730x; 1.4730x over previous
#include <cuda_runtime.h>
#include <cuda_bf16.h>
#include <cstdint>

// ---------------- problem constants ----------------
#define NDST0 67584
#define NDST1 6144
#define NDST2 1024
#define NE0   1013760
#define NE1   61440
#define NE2   5120
#define FIN   128
#define FH    256
#define NCLS  47

// ---------------- device scratch (referenced ONLY from device code) ----------------
__device__ float4 g_agg0 [NDST0 * FIN / 4];
__device__ float4 g_h1   [NDST0 * FH  / 4];
__device__ float4 g_agg1 [NDST1 * FH  / 4];
__device__ float4 g_h2   [NDST1 * FH  / 4];
__device__ float4 g_agg2 [NDST2 * FH  / 4];
__device__ int    g_deg  [NDST0];
__device__ int    g_cur  [NDST0];
__device__ int    g_off  [NDST0 + 1];
__device__ int    g_esrc [NE0];

// bf16 hi/lo split weights, transposed to [N][K] K-major ([op][n][k])
__device__ __nv_bfloat16 g_B0h[2 * FH * FIN];
__device__ __nv_bfloat16 g_B0l[2 * FH * FIN];
__device__ __nv_bfloat16 g_B1h[2 * FH * FH];
__device__ __nv_bfloat16 g_B1l[2 * FH * FH];

// ---------------- warp-MMA helpers (sm_80+ PTX; compiles for plain sm_103) ----------------
__device__ __forceinline__ uint32_t smem_u32(const void* p) {
    uint32_t a;
    asm("{ .reg .u64 t; cvta.to.shared.u64 t, %1; cvt.u32.u64 %0, t; }" : "=r"(a) : "l"(p));
    return a;
}
__device__ __forceinline__ void ldsm4(uint32_t* r, uint32_t addr) {
    asm volatile("ldmatrix.sync.aligned.m8n8.x4.shared.b16 {%0,%1,%2,%3}, [%4];"
                 : "=r"(r[0]), "=r"(r[1]), "=r"(r[2]), "=r"(r[3]) : "r"(addr) : "memory");
}
__device__ __forceinline__ void ldsm2(uint32_t* r, uint32_t addr) {
    asm volatile("ldmatrix.sync.aligned.m8n8.x2.shared.b16 {%0,%1}, [%2];"
                 : "=r"(r[0]), "=r"(r[1]) : "r"(addr) : "memory");
}
__device__ __forceinline__ void mma_bf16(float* d, const uint32_t* a, const uint32_t* b) {
    asm volatile("mma.sync.aligned.m16n8k16.row.col.f32.bf16.bf16.f32 "
                 "{%0,%1,%2,%3}, {%4,%5,%6,%7}, {%8,%9}, {%0,%1,%2,%3};"
                 : "+f"(d[0]), "+f"(d[1]), "+f"(d[2]), "+f"(d[3])
                 : "r"(a[0]), "r"(a[1]), "r"(a[2]), "r"(a[3]), "r"(b[0]), "r"(b[1]));
}
// 64B-row swizzle (rows of 32 bf16): conflict-free for ldmatrix + STS.64
__device__ __forceinline__ uint32_t sw64(uint32_t o) { return o ^ ((o >> 3) & 0x30); }

// ---------------- tiny utility kernels ----------------
__global__ void zero2_kernel(int n)
{
    int i = blockIdx.x * blockDim.x + threadIdx.x;
    if (i < n) { g_deg[i] = 0; g_cur[i] = 0; }
}

__global__ void hist_kernel(const int* __restrict__ dst, int E)
{
    int e = blockIdx.x * blockDim.x + threadIdx.x;
    if (e < E) atomicAdd(&g_deg[dst[e]], 1);
}

__global__ void scan_kernel(int n)
{
    __shared__ int warpsum[32];
    __shared__ int s_carry;
    const int tid  = threadIdx.x;
    const int lane = tid & 31;
    const int wid  = tid >> 5;
    if (tid == 0) s_carry = 0;
    __syncthreads();
    for (int base = 0; base < n; base += 1024) {
        int idx = base + tid;
        int v = (idx < n) ? g_deg[idx] : 0;
        int x = v;
#pragma unroll
        for (int st = 1; st < 32; st <<= 1) {
            int t = __shfl_up_sync(0xFFFFFFFFu, x, st);
            if (lane >= st) x += t;
        }
        if (lane == 31) warpsum[wid] = x;
        __syncthreads();
        if (wid == 0) {
            int w = warpsum[lane];
#pragma unroll
            for (int st = 1; st < 32; st <<= 1) {
                int t = __shfl_up_sync(0xFFFFFFFFu, w, st);
                if (lane >= st) w += t;
            }
            warpsum[lane] = w;
        }
        __syncthreads();
        int woff  = (wid > 0) ? warpsum[wid - 1] : 0;
        int carry = s_carry;
        if (idx < n) g_off[idx] = carry + woff + x - v;
        __syncthreads();
        if (tid == 0) s_carry = carry + warpsum[31];
        __syncthreads();
    }
    if (threadIdx.x == 0) g_off[n] = s_carry;
}

template <int REMAP>
__global__ void scatter_kernel(const int* __restrict__ src, const int* __restrict__ dst, int E,
                               const int* __restrict__ remap)
{
    int e = blockIdx.x * blockDim.x + threadIdx.x;
    if (e >= E) return;
    int d = dst[e];
    int p = g_off[d] + atomicAdd(&g_cur[d], 1);
    int s = src[e];
    g_esrc[p] = REMAP ? remap[s] : s;
}

// ---------------- mean aggregation: one warp per destination ----------------
template <int LAYER>
__global__ void agg_kernel(const float4* __restrict__ hExt, int n_dst)
{
    const float4* __restrict__ h4 =
        (LAYER == 0) ? hExt : (LAYER == 1) ? (const float4*)g_h1 : (const float4*)g_h2;
    float4* __restrict__ agg4 =
        (LAYER == 0) ? g_agg0 : (LAYER == 1) ? g_agg1 : g_agg2;
    const int VPL = (LAYER == 0) ? 1 : 2;
    const int F4  = VPL * 32;

    int w = (blockIdx.x * blockDim.x + threadIdx.x) >> 5;
    int lane = threadIdx.x & 31;
    if (w >= n_dst) return;
    int s = g_off[w], e = g_off[w + 1];

    float4 acc[VPL];
#pragma unroll
    for (int v = 0; v < VPL; v++) acc[v] = make_float4(0.f, 0.f, 0.f, 0.f);

    int i = s;
    for (; i + 1 < e; i += 2) {
        int r0 = g_esrc[i], r1 = g_esrc[i + 1];
#pragma unroll
        for (int v = 0; v < VPL; v++) {
            float4 x = h4[(size_t)r0 * F4 + v * 32 + lane];
            float4 y = h4[(size_t)r1 * F4 + v * 32 + lane];
            acc[v].x += x.x + y.x; acc[v].y += x.y + y.y;
            acc[v].z += x.z + y.z; acc[v].w += x.w + y.w;
        }
    }
    if (i < e) {
        int r0 = g_esrc[i];
#pragma unroll
        for (int v = 0; v < VPL; v++) {
            float4 x = h4[(size_t)r0 * F4 + v * 32 + lane];
            acc[v].x += x.x; acc[v].y += x.y; acc[v].z += x.z; acc[v].w += x.w;
        }
    }
    int cnt = e - s;
    float inv = 1.0f / (float)(cnt > 0 ? cnt : 1);
#pragma unroll
    for (int v = 0; v < VPL; v++) {
        agg4[(size_t)w * F4 + v * 32 + lane] =
            make_float4(acc[v].x * inv, acc[v].y * inv, acc[v].z * inv, acc[v].w * inv);
    }
}

// ---------------- weight prep: fp32 [K][N] -> bf16 hi/lo [N][K] ----------------
// FIX (R10 bug): destination pointers are resolved INSIDE device code.
// Host-side `g_B0h + off` passed the host shadow symbol -> silent ATS writes to
// host memory on GB300; device arrays stayed zero.
template <int L, int OP>
__global__ void w2bf_kernel(const float* __restrict__ W)
{
    const int K = (L == 0) ? FIN : FH;
    const int N = FH;
    __nv_bfloat16* __restrict__ outH =
        ((L == 0) ? g_B0h : g_B1h) + (size_t)OP * N * K;
    __nv_bfloat16* __restrict__ outL =
        ((L == 0) ? g_B0l : g_B1l) + (size_t)OP * N * K;
    int i = blockIdx.x * blockDim.x + threadIdx.x;
    if (i >= K * N) return;
    int k = i / N, n = i % N;
    float x = W[i];
    __nv_bfloat16 h = __float2bfloat16(x);
    __nv_bfloat16 l = __float2bfloat16(x - __bfloat162float(h));
    outH[n * K + k] = h;
    outL[n * K + k] = l;
}

// ---------------- warp-MMA dual-operand GEMM (3xBF16 split) ----------------
// C[128,128-tile of 256] = relu( A1@B1 + A2@B2 + bias ), fp32 accumulators.
// LAYER 0: A1 = emb rows via inodes (K=128), A2 = g_agg0, C = g_h1
// LAYER 1: A1 = g_h1 (K=256),                A2 = g_agg1, C = g_h2
// 256 threads = 8 warps; warp (wm, wn) computes 32x64; KTILE=32 per SMEM pass.
#define KTILE 32

template <int LAYER>
__global__ void __launch_bounds__(256) mma_gemm_kernel(
    const float* __restrict__ A1ext, const int* __restrict__ inodes,
    const float* __restrict__ bias)
{
    __shared__ int s_rows[128];
    __shared__ __align__(1024) __nv_bfloat16 sAh[128 * KTILE];
    __shared__ __align__(1024) __nv_bfloat16 sAl[128 * KTILE];
    __shared__ __align__(1024) __nv_bfloat16 sBh[128 * KTILE];
    __shared__ __align__(1024) __nv_bfloat16 sBl[128 * KTILE];

    const int tid  = threadIdx.x;
    const int lane = tid & 31;
    const int wid  = tid >> 5;
    const int wm   = wid & 3;       // 4 M-warps
    const int wn   = wid >> 2;      // 2 N-warps

    const int KOP   = (LAYER == 0) ? FIN : FH;
    const int TPO   = KOP / KTILE;
    const float* __restrict__ A1 = (LAYER == 0) ? A1ext : (const float*)g_h1;
    const float* __restrict__ A2 = (LAYER == 0) ? (const float*)g_agg0 : (const float*)g_agg1;
    float* __restrict__ C        = (LAYER == 0) ? (float*)g_h1 : (float*)g_h2;
    const __nv_bfloat16* __restrict__ BHg = (LAYER == 0) ? g_B0h : g_B1h;
    const __nv_bfloat16* __restrict__ BLg = (LAYER == 0) ? g_B0l : g_B1l;

    const int mbase = blockIdx.x * 128;
    const int n0cta = blockIdx.y * 128;

    if (tid < 128) s_rows[tid] = (LAYER == 0) ? __ldg(&inodes[mbase + tid]) : (mbase + tid);
    __syncthreads();

    const uint32_t bAh = smem_u32(sAh), bAl = smem_u32(sAl);
    const uint32_t bBh = smem_u32(sBh), bBl = smem_u32(sBl);

    float d[2][8][4];
#pragma unroll
    for (int mi = 0; mi < 2; mi++)
#pragma unroll
        for (int ni = 0; ni < 8; ni++)
#pragma unroll
            for (int j = 0; j < 4; j++) d[mi][ni][j] = 0.f;

    for (int t = 0; t < 2 * TPO; t++) {
        const int op = t / TPO;
        const int k0 = (t % TPO) * KTILE;
        const float* __restrict__ Asrc = op ? A2 : A1;

        // ---- A tile: 128 rows x 32 k, fp32 -> bf16 hi/lo, SW64 SMEM ----
#pragma unroll
        for (int it = 0; it < 4; it++) {
            int fi  = it * 256 + tid;           // float4 idx 0..1023
            int row = fi >> 3;
            int k4  = (fi & 7) << 2;
            int arow = op ? (mbase + row) : s_rows[row];
            float4 v = *(const float4*)(Asrc + (size_t)arow * KOP + k0 + k4);
            __nv_bfloat16 h0 = __float2bfloat16(v.x), h1 = __float2bfloat16(v.y);
            __nv_bfloat16 h2 = __float2bfloat16(v.z), h3 = __float2bfloat16(v.w);
            __nv_bfloat16 l0 = __float2bfloat16(v.x - __bfloat162float(h0));
            __nv_bfloat16 l1 = __float2bfloat16(v.y - __bfloat162float(h1));
            __nv_bfloat16 l2 = __float2bfloat16(v.z - __bfloat162float(h2));
            __nv_bfloat16 l3 = __float2bfloat16(v.w - __bfloat162float(h3));
            uint32_t off = sw64((uint32_t)(row * 64 + k4 * 2));
            __nv_bfloat162* ph = (__nv_bfloat162*)((char*)sAh + off);
            __nv_bfloat162* pl = (__nv_bfloat162*)((char*)sAl + off);
            ph[0] = __nv_bfloat162(h0, h1); ph[1] = __nv_bfloat162(h2, h3);
            pl[0] = __nv_bfloat162(l0, l1); pl[1] = __nv_bfloat162(l2, l3);
        }
        // ---- B tile: 128 n-rows x 32 k, bf16 [N][KOP] global, SW64 SMEM ----
        const __nv_bfloat16* __restrict__ BH = BHg + (size_t)op * FH * KOP;
        const __nv_bfloat16* __restrict__ BL = BLg + (size_t)op * FH * KOP;
#pragma unroll
        for (int it = 0; it < 4; it++) {
            int ci = it * 256 + tid;            // 8B-chunk idx 0..1023
            int n  = ci >> 3;                   // 0..127
            int kc = (ci & 7) << 2;             // 0..28
            uint32_t off = sw64((uint32_t)(n * 64 + kc * 2));
            size_t gi = (size_t)(n0cta + n) * KOP + k0 + kc;
            *(uint64_t*)((char*)sBh + off) = *(const uint64_t*)(BH + gi);
            *(uint64_t*)((char*)sBl + off) = *(const uint64_t*)(BL + gi);
        }
        __syncthreads();

        // ---- compute: 2 k16-steps, 3 split terms each ----
#pragma unroll
        for (int k16 = 0; k16 < 2; k16++) {
            const int kb = k16 * 32;
            const uint32_t aoff0 = sw64((uint32_t)((wm * 32 + (lane & 15)) * 64 + kb + (lane >> 4) * 16));
            const uint32_t aoff1 = sw64((uint32_t)((wm * 32 + 16 + (lane & 15)) * 64 + kb + (lane >> 4) * 16));
            uint32_t ah[2][4], al[2][4], bh[8][2], bl[8][2];
            ldsm4(ah[0], bAh + aoff0);
            ldsm4(ah[1], bAh + aoff1);
            ldsm4(al[0], bAl + aoff0);
            ldsm4(al[1], bAl + aoff1);
#pragma unroll
            for (int ni = 0; ni < 8; ni++) {
                uint32_t boff = sw64((uint32_t)((wn * 64 + ni * 8 + (lane & 7)) * 64 + kb + ((lane >> 3) & 1) * 16));
                ldsm2(bh[ni], bBh + boff);
                ldsm2(bl[ni], bBl + boff);
            }
#pragma unroll
            for (int mi = 0; mi < 2; mi++)
#pragma unroll
                for (int ni = 0; ni < 8; ni++) {
                    mma_bf16(d[mi][ni], ah[mi], bh[ni]);   // hi*hi
                    mma_bf16(d[mi][ni], al[mi], bh[ni]);   // lo*hi
                    mma_bf16(d[mi][ni], ah[mi], bl[ni]);   // hi*lo
                }
        }
        __syncthreads();
    }

    // ---- epilogue: bias + relu, direct global stores ----
#pragma unroll
    for (int mi = 0; mi < 2; mi++) {
        int row0 = mbase + wm * 32 + mi * 16 + (lane >> 2);
#pragma unroll
        for (int ni = 0; ni < 8; ni++) {
            int col = n0cta + wn * 64 + ni * 8 + (lane & 3) * 2;
            float2 bv = *(const float2*)(bias + col);
            float2 v0, v1;
            v0.x = fmaxf(d[mi][ni][0] + bv.x, 0.f);
            v0.y = fmaxf(d[mi][ni][1] + bv.y, 0.f);
            v1.x = fmaxf(d[mi][ni][2] + bv.x, 0.f);
            v1.y = fmaxf(d[mi][ni][3] + bv.y, 0.f);
            *(float2*)(C + (size_t)row0 * FH + col)       = v0;
            *(float2*)(C + (size_t)(row0 + 8) * FH + col) = v1;
        }
    }
}

// ---------------- layer 2 (tiny, N=47) ----------------
__global__ void layer2_kernel(const float* __restrict__ Ws, const float* __restrict__ Wn,
                              const float* __restrict__ b, float* __restrict__ out)
{
    int m = blockIdx.x;
    int n = threadIdx.x;
    if (n >= NCLS) return;
    float acc = b[n];
    const float* hr = (const float*)g_h2   + (size_t)m * FH;
    const float* ar = (const float*)g_agg2 + (size_t)m * FH;
#pragma unroll 4
    for (int k = 0; k < FH; k++)
        acc += hr[k] * Ws[k * NCLS + n] + ar[k] * Wn[k * NCLS + n];
    out[m * NCLS + n] = acc;
}

// ---------------- orchestration (kernel launches ONLY — graph-capturable) ----------------
extern "C" void kernel_launch(void* const* d_in, const int* in_sizes, int n_in,
                              void* d_out, int out_size)
{
    (void)in_sizes; (void)n_in; (void)out_size;
    const float* emb         = (const float*)d_in[0];
    const int*   input_nodes = (const int*)  d_in[1];
    const int*   src0        = (const int*)  d_in[2];
    const int*   dst0        = (const int*)  d_in[3];
    const int*   src1        = (const int*)  d_in[4];
    const int*   dst1        = (const int*)  d_in[5];
    const int*   src2        = (const int*)  d_in[6];
    const int*   dst2        = (const int*)  d_in[7];
    const float* Ws0         = (const float*)d_in[8];
    const float* Wn0         = (const float*)d_in[9];
    const float* b0          = (const float*)d_in[10];
    const float* Ws1         = (const float*)d_in[11];
    const float* Wn1         = (const float*)d_in[12];
    const float* b1          = (const float*)d_in[13];
    const float* Ws2         = (const float*)d_in[14];
    const float* Wn2         = (const float*)d_in[15];
    const float* b2          = (const float*)d_in[16];
    float* out = (float*)d_out;

    const int TB = 256;

    // weight prep (bf16 hi/lo + transpose): op0 = Wself, op1 = Wneigh
    w2bf_kernel<0, 0><<<(FIN * FH + TB - 1) / TB, TB>>>(Ws0);
    w2bf_kernel<0, 1><<<(FIN * FH + TB - 1) / TB, TB>>>(Wn0);
    w2bf_kernel<1, 0><<<(FH * FH + TB - 1) / TB, TB>>>(Ws1);
    w2bf_kernel<1, 1><<<(FH * FH + TB - 1) / TB, TB>>>(Wn1);

    // ---- layer 0 ----
    zero2_kernel<<<(NDST0 + TB - 1) / TB, TB>>>(NDST0);
    hist_kernel<<<(NE0 + TB - 1) / TB, TB>>>(dst0, NE0);
    scan_kernel<<<1, 1024>>>(NDST0);
    scatter_kernel<1><<<(NE0 + TB - 1) / TB, TB>>>(src0, dst0, NE0, input_nodes);
    agg_kernel<0><<<(NDST0 + 7) / 8, TB>>>((const float4*)emb, NDST0);
    {
        dim3 grid(NDST0 / 128, FH / 128);
        mma_gemm_kernel<0><<<grid, 256>>>(emb, input_nodes, b0);
    }

    // ---- layer 1 ----
    zero2_kernel<<<(NDST1 + TB - 1) / TB, TB>>>(NDST1);
    hist_kernel<<<(NE1 + TB - 1) / TB, TB>>>(dst1, NE1);
    scan_kernel<<<1, 1024>>>(NDST1);
    scatter_kernel<0><<<(NE1 + TB - 1) / TB, TB>>>(src1, dst1, NE1, input_nodes);
    agg_kernel<1><<<(NDST1 + 7) / 8, TB>>>((const float4*)emb, NDST1);
    {
        dim3 grid(NDST1 / 128, FH / 128);
        mma_gemm_kernel<1><<<grid, 256>>>(emb, input_nodes, b1);
    }

    // ---- layer 2 ----
    zero2_kernel<<<(NDST2 + TB - 1) / TB, TB>>>(NDST2);
    hist_kernel<<<(NE2 + TB - 1) / TB, TB>>>(dst2, NE2);
    scan_kernel<<<1, 1024>>>(NDST2);
    scatter_kernel<0><<<(NE2 + TB - 1) / TB, TB>>>(src2, dst2, NE2, input_nodes);
    agg_kernel<2><<<(NDST2 + 7) / 8, TB>>>((const float4*)emb, NDST2);
    layer2_kernel<<<NDST2, 64>>>(Ws2, Wn2, b2, out);
}

// round 16
// speedup vs baseline: 1.4984x; 1.0172x over previous
#include <cuda_runtime.h>
#include <cuda_bf16.h>
#include <cstdint>

// ---------------- problem constants ----------------
#define NDST0 67584
#define NDST1 6144
#define NDST2 1024
#define NE0   1013760
#define NE1   61440
#define NE2   5120
#define FIN   128
#define FH    256
#define NCLS  47

// ---------------- device scratch (referenced ONLY from device code) ----------------
__device__ float4 g_agg0 [NDST0 * FIN / 4];
__device__ float4 g_h1   [NDST0 * FH  / 4];
__device__ float4 g_agg1 [NDST1 * FH  / 4];
__device__ float4 g_h2   [NDST1 * FH  / 4];
__device__ float4 g_agg2 [NDST2 * FH  / 4];
__device__ int    g_deg  [NDST0];
__device__ int    g_cur  [NDST0];
__device__ int    g_off  [NDST0 + 1];
__device__ int    g_esrc [NE0];

// bf16 hi/lo split weights, transposed to [N][K] K-major ([op][n][k])
__device__ __nv_bfloat16 g_B0h[2 * FH * FIN];
__device__ __nv_bfloat16 g_B0l[2 * FH * FIN];
__device__ __nv_bfloat16 g_B1h[2 * FH * FH];
__device__ __nv_bfloat16 g_B1l[2 * FH * FH];

// ---------------- warp-MMA helpers (sm_80+ PTX; compiles for plain sm_103) ----------------
__device__ __forceinline__ uint32_t smem_u32(const void* p) {
    uint32_t a;
    asm("{ .reg .u64 t; cvta.to.shared.u64 t, %1; cvt.u32.u64 %0, t; }" : "=r"(a) : "l"(p));
    return a;
}
__device__ __forceinline__ void ldsm4(uint32_t* r, uint32_t addr) {
    asm volatile("ldmatrix.sync.aligned.m8n8.x4.shared.b16 {%0,%1,%2,%3}, [%4];"
                 : "=r"(r[0]), "=r"(r[1]), "=r"(r[2]), "=r"(r[3]) : "r"(addr) : "memory");
}
__device__ __forceinline__ void ldsm2(uint32_t* r, uint32_t addr) {
    asm volatile("ldmatrix.sync.aligned.m8n8.x2.shared.b16 {%0,%1}, [%2];"
                 : "=r"(r[0]), "=r"(r[1]) : "r"(addr) : "memory");
}
__device__ __forceinline__ void mma_bf16(float* d, const uint32_t* a, const uint32_t* b) {
    asm volatile("mma.sync.aligned.m16n8k16.row.col.f32.bf16.bf16.f32 "
                 "{%0,%1,%2,%3}, {%4,%5,%6,%7}, {%8,%9}, {%0,%1,%2,%3};"
                 : "+f"(d[0]), "+f"(d[1]), "+f"(d[2]), "+f"(d[3])
                 : "r"(a[0]), "r"(a[1]), "r"(a[2]), "r"(a[3]), "r"(b[0]), "r"(b[1]));
}
// 64B-row swizzle (rows of 32 bf16): conflict-free for ldmatrix + STS.64
__device__ __forceinline__ uint32_t sw64(uint32_t o) { return o ^ ((o >> 3) & 0x30); }

// ---------------- tiny utility kernels ----------------
__global__ void zero2_kernel(int n)
{
    int i = blockIdx.x * blockDim.x + threadIdx.x;
    if (i < n) { g_deg[i] = 0; g_cur[i] = 0; }
}

__global__ void hist_kernel(const int* __restrict__ dst, int E)
{
    int e = blockIdx.x * blockDim.x + threadIdx.x;
    if (e < E) atomicAdd(&g_deg[dst[e]], 1);
}

__global__ void scan_kernel(int n)
{
    __shared__ int warpsum[32];
    __shared__ int s_carry;
    const int tid  = threadIdx.x;
    const int lane = tid & 31;
    const int wid  = tid >> 5;
    if (tid == 0) s_carry = 0;
    __syncthreads();
    for (int base = 0; base < n; base += 1024) {
        int idx = base + tid;
        int v = (idx < n) ? g_deg[idx] : 0;
        int x = v;
#pragma unroll
        for (int st = 1; st < 32; st <<= 1) {
            int t = __shfl_up_sync(0xFFFFFFFFu, x, st);
            if (lane >= st) x += t;
        }
        if (lane == 31) warpsum[wid] = x;
        __syncthreads();
        if (wid == 0) {
            int w = warpsum[lane];
#pragma unroll
            for (int st = 1; st < 32; st <<= 1) {
                int t = __shfl_up_sync(0xFFFFFFFFu, w, st);
                if (lane >= st) w += t;
            }
            warpsum[lane] = w;
        }
        __syncthreads();
        int woff  = (wid > 0) ? warpsum[wid - 1] : 0;
        int carry = s_carry;
        if (idx < n) g_off[idx] = carry + woff + x - v;
        __syncthreads();
        if (tid == 0) s_carry = carry + warpsum[31];
        __syncthreads();
    }
    if (threadIdx.x == 0) g_off[n] = s_carry;
}

template <int REMAP>
__global__ void scatter_kernel(const int* __restrict__ src, const int* __restrict__ dst, int E,
                               const int* __restrict__ remap)
{
    int e = blockIdx.x * blockDim.x + threadIdx.x;
    if (e >= E) return;
    int d = dst[e];
    int p = g_off[d] + atomicAdd(&g_cur[d], 1);
    int s = src[e];
    g_esrc[p] = REMAP ? remap[s] : s;
}

// ---------------- mean aggregation: one warp per destination (4x edge unroll) ----------------
template <int LAYER>
__global__ void agg_kernel(const float4* __restrict__ hExt, int n_dst)
{
    const float4* __restrict__ h4 =
        (LAYER == 0) ? hExt : (LAYER == 1) ? (const float4*)g_h1 : (const float4*)g_h2;
    float4* __restrict__ agg4 =
        (LAYER == 0) ? g_agg0 : (LAYER == 1) ? g_agg1 : g_agg2;
    const int VPL = (LAYER == 0) ? 1 : 2;
    const int F4  = VPL * 32;

    int w = (blockIdx.x * blockDim.x + threadIdx.x) >> 5;
    int lane = threadIdx.x & 31;
    if (w >= n_dst) return;
    int s = g_off[w], e = g_off[w + 1];

    float4 acc[VPL];
#pragma unroll
    for (int v = 0; v < VPL; v++) acc[v] = make_float4(0.f, 0.f, 0.f, 0.f);

    int i = s;
    for (; i + 3 < e; i += 4) {           // 4x unroll for MLP
        int r0 = g_esrc[i], r1 = g_esrc[i + 1];
        int r2 = g_esrc[i + 2], r3 = g_esrc[i + 3];
#pragma unroll
        for (int v = 0; v < VPL; v++) {
            float4 x = h4[(size_t)r0 * F4 + v * 32 + lane];
            float4 y = h4[(size_t)r1 * F4 + v * 32 + lane];
            float4 z = h4[(size_t)r2 * F4 + v * 32 + lane];
            float4 u = h4[(size_t)r3 * F4 + v * 32 + lane];
            acc[v].x += (x.x + y.x) + (z.x + u.x);
            acc[v].y += (x.y + y.y) + (z.y + u.y);
            acc[v].z += (x.z + y.z) + (z.z + u.z);
            acc[v].w += (x.w + y.w) + (z.w + u.w);
        }
    }
    for (; i < e; i++) {
        int r0 = g_esrc[i];
#pragma unroll
        for (int v = 0; v < VPL; v++) {
            float4 x = h4[(size_t)r0 * F4 + v * 32 + lane];
            acc[v].x += x.x; acc[v].y += x.y; acc[v].z += x.z; acc[v].w += x.w;
        }
    }
    int cnt = e - s;
    float inv = 1.0f / (float)(cnt > 0 ? cnt : 1);
#pragma unroll
    for (int v = 0; v < VPL; v++) {
        agg4[(size_t)w * F4 + v * 32 + lane] =
            make_float4(acc[v].x * inv, acc[v].y * inv, acc[v].z * inv, acc[v].w * inv);
    }
}

// ---------------- weight prep (single merged kernel) ----------------
// fp32 [K][N] -> bf16 hi/lo [N][K], all four weight matrices in one launch.
__global__ void w2bf_all_kernel(const float* __restrict__ Ws0, const float* __restrict__ Wn0,
                                const float* __restrict__ Ws1, const float* __restrict__ Wn1)
{
    int i = blockIdx.x * blockDim.x + threadIdx.x;
    if (i >= 2 * FIN * FH + 2 * FH * FH) return;

    const float* W;
    __nv_bfloat16 *outH, *outL;
    int K, li;
    if (i < FIN * FH) {
        W = Ws0; outH = g_B0h; outL = g_B0l; K = FIN; li = i;
    } else if (i < 2 * FIN * FH) {
        W = Wn0; outH = g_B0h + FH * FIN; outL = g_B0l + FH * FIN; K = FIN; li = i - FIN * FH;
    } else if (i < 2 * FIN * FH + FH * FH) {
        W = Ws1; outH = g_B1h; outL = g_B1l; K = FH; li = i - 2 * FIN * FH;
    } else {
        W = Wn1; outH = g_B1h + FH * FH; outL = g_B1l + FH * FH; K = FH; li = i - 2 * FIN * FH - FH * FH;
    }
    int k = li / FH, n = li % FH;
    float x = W[li];
    __nv_bfloat16 h = __float2bfloat16(x);
    __nv_bfloat16 l = __float2bfloat16(x - __bfloat162float(h));
    outH[n * K + k] = h;
    outL[n * K + k] = l;
}

// ---------------- warp-MMA dual-operand GEMM (3xBF16 split) ----------------
// C[128,128-tile of 256] = relu( A1@B1 + A2@B2 + bias ), fp32 accumulators.
// LAYER 0: A1 = emb rows via inodes (K=128), A2 = g_agg0, C = g_h1
// LAYER 1: A1 = g_h1 (K=256),                A2 = g_agg1, C = g_h2
// 256 threads = 8 warps; warp (wm, wn) computes 32x64; KTILE=32 per SMEM pass.
// (Round-12 proven configuration — reverted from the 512-thread variant.)
#define KTILE 32

template <int LAYER>
__global__ void __launch_bounds__(256) mma_gemm_kernel(
    const float* __restrict__ A1ext, const int* __restrict__ inodes,
    const float* __restrict__ bias)
{
    __shared__ int s_rows[128];
    __shared__ __align__(1024) __nv_bfloat16 sAh[128 * KTILE];
    __shared__ __align__(1024) __nv_bfloat16 sAl[128 * KTILE];
    __shared__ __align__(1024) __nv_bfloat16 sBh[128 * KTILE];
    __shared__ __align__(1024) __nv_bfloat16 sBl[128 * KTILE];

    const int tid  = threadIdx.x;
    const int lane = tid & 31;
    const int wid  = tid >> 5;
    const int wm   = wid & 3;       // 4 M-warps
    const int wn   = wid >> 2;      // 2 N-warps

    const int KOP   = (LAYER == 0) ? FIN : FH;
    const int TPO   = KOP / KTILE;
    const float* __restrict__ A1 = (LAYER == 0) ? A1ext : (const float*)g_h1;
    const float* __restrict__ A2 = (LAYER == 0) ? (const float*)g_agg0 : (const float*)g_agg1;
    float* __restrict__ C        = (LAYER == 0) ? (float*)g_h1 : (float*)g_h2;
    const __nv_bfloat16* __restrict__ BHg = (LAYER == 0) ? g_B0h : g_B1h;
    const __nv_bfloat16* __restrict__ BLg = (LAYER == 0) ? g_B0l : g_B1l;

    const int mbase = blockIdx.x * 128;
    const int n0cta = blockIdx.y * 128;

    if (tid < 128) s_rows[tid] = (LAYER == 0) ? __ldg(&inodes[mbase + tid]) : (mbase + tid);
    __syncthreads();

    const uint32_t bAh = smem_u32(sAh), bAl = smem_u32(sAl);
    const uint32_t bBh = smem_u32(sBh), bBl = smem_u32(sBl);

    float d[2][8][4];
#pragma unroll
    for (int mi = 0; mi < 2; mi++)
#pragma unroll
        for (int ni = 0; ni < 8; ni++)
#pragma unroll
            for (int j = 0; j < 4; j++) d[mi][ni][j] = 0.f;

    for (int t = 0; t < 2 * TPO; t++) {
        const int op = t / TPO;
        const int k0 = (t % TPO) * KTILE;
        const float* __restrict__ Asrc = op ? A2 : A1;

        // ---- A tile: 128 rows x 32 k, fp32 -> bf16 hi/lo, SW64 SMEM ----
#pragma unroll
        for (int it = 0; it < 4; it++) {
            int fi  = it * 256 + tid;           // float4 idx 0..1023
            int row = fi >> 3;
            int k4  = (fi & 7) << 2;
            int arow = op ? (mbase + row) : s_rows[row];
            float4 v = *(const float4*)(Asrc + (size_t)arow * KOP + k0 + k4);
            __nv_bfloat16 h0 = __float2bfloat16(v.x), h1 = __float2bfloat16(v.y);
            __nv_bfloat16 h2 = __float2bfloat16(v.z), h3 = __float2bfloat16(v.w);
            __nv_bfloat16 l0 = __float2bfloat16(v.x - __bfloat162float(h0));
            __nv_bfloat16 l1 = __float2bfloat16(v.y - __bfloat162float(h1));
            __nv_bfloat16 l2 = __float2bfloat16(v.z - __bfloat162float(h2));
            __nv_bfloat16 l3 = __float2bfloat16(v.w - __bfloat162float(h3));
            uint32_t off = sw64((uint32_t)(row * 64 + k4 * 2));
            __nv_bfloat162* ph = (__nv_bfloat162*)((char*)sAh + off);
            __nv_bfloat162* pl = (__nv_bfloat162*)((char*)sAl + off);
            ph[0] = __nv_bfloat162(h0, h1); ph[1] = __nv_bfloat162(h2, h3);
            pl[0] = __nv_bfloat162(l0, l1); pl[1] = __nv_bfloat162(l2, l3);
        }
        // ---- B tile: 128 n-rows x 32 k, bf16 [N][KOP] global, SW64 SMEM ----
        const __nv_bfloat16* __restrict__ BH = BHg + (size_t)op * FH * KOP;
        const __nv_bfloat16* __restrict__ BL = BLg + (size_t)op * FH * KOP;
#pragma unroll
        for (int it = 0; it < 4; it++) {
            int ci = it * 256 + tid;            // 8B-chunk idx 0..1023
            int n  = ci >> 3;                   // 0..127
            int kc = (ci & 7) << 2;             // 0..28
            uint32_t off = sw64((uint32_t)(n * 64 + kc * 2));
            size_t gi = (size_t)(n0cta + n) * KOP + k0 + kc;
            *(uint64_t*)((char*)sBh + off) = *(const uint64_t*)(BH + gi);
            *(uint64_t*)((char*)sBl + off) = *(const uint64_t*)(BL + gi);
        }
        __syncthreads();

        // ---- compute: 2 k16-steps, 3 split terms each ----
#pragma unroll
        for (int k16 = 0; k16 < 2; k16++) {
            const int kb = k16 * 32;
            const uint32_t aoff0 = sw64((uint32_t)((wm * 32 + (lane & 15)) * 64 + kb + (lane >> 4) * 16));
            const uint32_t aoff1 = sw64((uint32_t)((wm * 32 + 16 + (lane & 15)) * 64 + kb + (lane >> 4) * 16));
            uint32_t ah[2][4], al[2][4], bh[8][2], bl[8][2];
            ldsm4(ah[0], bAh + aoff0);
            ldsm4(ah[1], bAh + aoff1);
            ldsm4(al[0], bAl + aoff0);
            ldsm4(al[1], bAl + aoff1);
#pragma unroll
            for (int ni = 0; ni < 8; ni++) {
                uint32_t boff = sw64((uint32_t)((wn * 64 + ni * 8 + (lane & 7)) * 64 + kb + ((lane >> 3) & 1) * 16));
                ldsm2(bh[ni], bBh + boff);
                ldsm2(bl[ni], bBl + boff);
            }
#pragma unroll
            for (int mi = 0; mi < 2; mi++)
#pragma unroll
                for (int ni = 0; ni < 8; ni++) {
                    mma_bf16(d[mi][ni], ah[mi], bh[ni]);   // hi*hi
                    mma_bf16(d[mi][ni], al[mi], bh[ni]);   // lo*hi
                    mma_bf16(d[mi][ni], ah[mi], bl[ni]);   // hi*lo
                }
        }
        __syncthreads();
    }

    // ---- epilogue: bias + relu, direct global stores ----
#pragma unroll
    for (int mi = 0; mi < 2; mi++) {
        int row0 = mbase + wm * 32 + mi * 16 + (lane >> 2);
#pragma unroll
        for (int ni = 0; ni < 8; ni++) {
            int col = n0cta + wn * 64 + ni * 8 + (lane & 3) * 2;
            float2 bv = *(const float2*)(bias + col);
            float2 v0, v1;
            v0.x = fmaxf(d[mi][ni][0] + bv.x, 0.f);
            v0.y = fmaxf(d[mi][ni][1] + bv.y, 0.f);
            v1.x = fmaxf(d[mi][ni][2] + bv.x, 0.f);
            v1.y = fmaxf(d[mi][ni][3] + bv.y, 0.f);
            *(float2*)(C + (size_t)row0 * FH + col)       = v0;
            *(float2*)(C + (size_t)(row0 + 8) * FH + col) = v1;
        }
    }
}

// ---------------- layer 2 (tiny, N=47) ----------------
__global__ void layer2_kernel(const float* __restrict__ Ws, const float* __restrict__ Wn,
                              const float* __restrict__ b, float* __restrict__ out)
{
    int m = blockIdx.x;
    int n = threadIdx.x;
    if (n >= NCLS) return;
    float acc = b[n];
    const float* hr = (const float*)g_h2   + (size_t)m * FH;
    const float* ar = (const float*)g_agg2 + (size_t)m * FH;
#pragma unroll 4
    for (int k = 0; k < FH; k++)
        acc += hr[k] * Ws[k * NCLS + n] + ar[k] * Wn[k * NCLS + n];
    out[m * NCLS + n] = acc;
}

// ---------------- orchestration (kernel launches ONLY — graph-capturable) ----------------
extern "C" void kernel_launch(void* const* d_in, const int* in_sizes, int n_in,
                              void* d_out, int out_size)
{
    (void)in_sizes; (void)n_in; (void)out_size;
    const float* emb         = (const float*)d_in[0];
    const int*   input_nodes = (const int*)  d_in[1];
    const int*   src0        = (const int*)  d_in[2];
    const int*   dst0        = (const int*)  d_in[3];
    const int*   src1        = (const int*)  d_in[4];
    const int*   dst1        = (const int*)  d_in[5];
    const int*   src2        = (const int*)  d_in[6];
    const int*   dst2        = (const int*)  d_in[7];
    const float* Ws0         = (const float*)d_in[8];
    const float* Wn0         = (const float*)d_in[9];
    const float* b0          = (const float*)d_in[10];
    const float* Ws1         = (const float*)d_in[11];
    const float* Wn1         = (const float*)d_in[12];
    const float* b1          = (const float*)d_in[13];
    const float* Ws2         = (const float*)d_in[14];
    const float* Wn2         = (const float*)d_in[15];
    const float* b2          = (const float*)d_in[16];
    float* out = (float*)d_out;

    const int TB = 256;

    // weight prep (bf16 hi/lo + transpose), single launch for all four matrices
    {
        int total = 2 * FIN * FH + 2 * FH * FH;
        w2bf_all_kernel<<<(total + TB - 1) / TB, TB>>>(Ws0, Wn0, Ws1, Wn1);
    }

    // ---- layer 0 ----
    zero2_kernel<<<(NDST0 + TB - 1) / TB, TB>>>(NDST0);
    hist_kernel<<<(NE0 + TB - 1) / TB, TB>>>(dst0, NE0);
    scan_kernel<<<1, 1024>>>(NDST0);
    scatter_kernel<1><<<(NE0 + TB - 1) / TB, TB>>>(src0, dst0, NE0, input_nodes);
    agg_kernel<0><<<(NDST0 + 7) / 8, TB>>>((const float4*)emb, NDST0);
    {
        dim3 grid(NDST0 / 128, FH / 128);
        mma_gemm_kernel<0><<<grid, 256>>>(emb, input_nodes, b0);
    }

    // ---- layer 1 ----
    zero2_kernel<<<(NDST1 + TB - 1) / TB, TB>>>(NDST1);
    hist_kernel<<<(NE1 + TB - 1) / TB, TB>>>(dst1, NE1);
    scan_kernel<<<1, 1024>>>(NDST1);
    scatter_kernel<0><<<(NE1 + TB - 1) / TB, TB>>>(src1, dst1, NE1, input_nodes);
    agg_kernel<1><<<(NDST1 + 7) / 8, TB>>>((const float4*)emb, NDST1);
    {
        dim3 grid(NDST1 / 128, FH / 128);
        mma_gemm_kernel<1><<<grid, 256>>>(emb, input_nodes, b1);
    }

    // ---- layer 2 ----
    zero2_kernel<<<(NDST2 + TB - 1) / TB, TB>>>(NDST2);
    hist_kernel<<<(NE2 + TB - 1) / TB, TB>>>(dst2, NE2);
    scan_kernel<<<1, 1024>>>(NDST2);
    scatter_kernel<0><<<(NE2 + TB - 1) / TB, TB>>>(src2, dst2, NE2, input_nodes);
    agg_kernel<2><<<(NDST2 + 7) / 8, TB>>>((const float4*)emb, NDST2);
    layer2_kernel<<<NDST2, 64>>>(Ws2, Wn2, b2, out);
}

// round 17
// speedup vs baseline: 1.5928x; 1.0630x over previous
#include <cuda_runtime.h>
#include <cuda_bf16.h>
#include <cstdint>

// ---------------- problem constants ----------------
#define NDST0 67584
#define NDST1 6144
#define NDST2 1024
#define NE0   1013760
#define NE1   61440
#define NE2   5120
#define FIN   128
#define FH    256
#define NCLS  47

// ---------------- device scratch (referenced ONLY from device code) ----------------
__device__ float4 g_agg0 [NDST0 * FIN / 4];
__device__ float4 g_h1   [NDST0 * FH  / 4];
__device__ float4 g_agg1 [NDST1 * FH  / 4];
__device__ float4 g_h2   [NDST1 * FH  / 4];
__device__ float4 g_agg2 [NDST2 * FH  / 4];
__device__ int    g_deg  [NDST0];
__device__ int    g_cur  [NDST0];
__device__ int    g_off  [NDST0 + 1];
__device__ int    g_esrc [NE0];
__device__ int    g_bsum [128];               // per-block partial sums for multi-block scan

// bf16 hi/lo split weights, transposed to [N][K] K-major ([op][n][k])
__device__ __nv_bfloat16 g_B0h[2 * FH * FIN];
__device__ __nv_bfloat16 g_B0l[2 * FH * FIN];
__device__ __nv_bfloat16 g_B1h[2 * FH * FH];
__device__ __nv_bfloat16 g_B1l[2 * FH * FH];

// ---------------- warp-MMA helpers (sm_80+ PTX; compiles for plain sm_103) ----------------
__device__ __forceinline__ uint32_t smem_u32(const void* p) {
    uint32_t a;
    asm("{ .reg .u64 t; cvta.to.shared.u64 t, %1; cvt.u32.u64 %0, t; }" : "=r"(a) : "l"(p));
    return a;
}
__device__ __forceinline__ void ldsm4(uint32_t* r, uint32_t addr) {
    asm volatile("ldmatrix.sync.aligned.m8n8.x4.shared.b16 {%0,%1,%2,%3}, [%4];"
                 : "=r"(r[0]), "=r"(r[1]), "=r"(r[2]), "=r"(r[3]) : "r"(addr) : "memory");
}
__device__ __forceinline__ void ldsm2(uint32_t* r, uint32_t addr) {
    asm volatile("ldmatrix.sync.aligned.m8n8.x2.shared.b16 {%0,%1}, [%2];"
                 : "=r"(r[0]), "=r"(r[1]) : "r"(addr) : "memory");
}
__device__ __forceinline__ void mma_bf16(float* d, const uint32_t* a, const uint32_t* b) {
    asm volatile("mma.sync.aligned.m16n8k16.row.col.f32.bf16.bf16.f32 "
                 "{%0,%1,%2,%3}, {%4,%5,%6,%7}, {%8,%9}, {%0,%1,%2,%3};"
                 : "+f"(d[0]), "+f"(d[1]), "+f"(d[2]), "+f"(d[3])
                 : "r"(a[0]), "r"(a[1]), "r"(a[2]), "r"(a[3]), "r"(b[0]), "r"(b[1]));
}
// 64B-row swizzle (rows of 32 bf16): conflict-free for ldmatrix + STS.64
__device__ __forceinline__ uint32_t sw64(uint32_t o) { return o ^ ((o >> 3) & 0x30); }

// ---------------- tiny utility kernels ----------------
__global__ void zero2_kernel(int n)
{
    int i = blockIdx.x * blockDim.x + threadIdx.x;
    if (i < n) { g_deg[i] = 0; g_cur[i] = 0; }
}

__global__ void hist_kernel(const int* __restrict__ dst, int E)
{
    int e = blockIdx.x * blockDim.x + threadIdx.x;
    if (e < E) atomicAdd(&g_deg[dst[e]], 1);
}

// ---------------- multi-block exclusive scan: g_deg[0..n) -> g_off[0..n] ----------------
// Phase 1: each 1024-block scans its chunk locally into g_off, block total -> g_bsum.
__global__ void scan_partial_kernel(int n)
{
    __shared__ int warpsum[32];
    const int tid  = threadIdx.x;
    const int lane = tid & 31;
    const int wid  = tid >> 5;
    const int idx  = blockIdx.x * 1024 + tid;

    int v = (idx < n) ? g_deg[idx] : 0;
    int x = v;
#pragma unroll
    for (int st = 1; st < 32; st <<= 1) {
        int t = __shfl_up_sync(0xFFFFFFFFu, x, st);
        if (lane >= st) x += t;
    }
    if (lane == 31) warpsum[wid] = x;
    __syncthreads();
    if (wid == 0) {
        int w = warpsum[lane];
#pragma unroll
        for (int st = 1; st < 32; st <<= 1) {
            int t = __shfl_up_sync(0xFFFFFFFFu, w, st);
            if (lane >= st) w += t;
        }
        warpsum[lane] = w;   // inclusive warp totals
    }
    __syncthreads();
    int woff = (wid > 0) ? warpsum[wid - 1] : 0;
    if (idx < n) g_off[idx] = woff + x - v;       // block-local exclusive
    if (tid == 1023) g_bsum[blockIdx.x] = woff + x;  // block total
}

// Phase 2: 1 block scans g_bsum[0..nb) exclusively (nb <= 128).
__global__ void scan_bsums_kernel(int nb)
{
    const int lane = threadIdx.x & 31;
    const int wid  = threadIdx.x >> 5;
    __shared__ int ws[4];
    int idx = threadIdx.x;                 // 128 threads
    int v = (idx < nb) ? g_bsum[idx] : 0;
    int x = v;
#pragma unroll
    for (int st = 1; st < 32; st <<= 1) {
        int t = __shfl_up_sync(0xFFFFFFFFu, x, st);
        if (lane >= st) x += t;
    }
    if (lane == 31) ws[wid] = x;
    __syncthreads();
    int woff = 0;
    for (int w = 0; w < 4; w++) if (w < wid) woff += ws[w];
    if (idx < nb) g_bsum[idx] = woff + x - v;   // exclusive block offsets
}

// Phase 3: add block offsets; thread n writes total.
__global__ void scan_addoff_kernel(int n)
{
    int idx = blockIdx.x * 1024 + threadIdx.x;
    int boff = g_bsum[blockIdx.x];
    if (idx < n) g_off[idx] += boff;
    // last block, last active thread writes g_off[n] = total of all degrees
    if (idx == n - 1) g_off[n] = g_off[n - 1] + g_deg[n - 1];
}

template <int REMAP>
__global__ void scatter_kernel(const int* __restrict__ src, const int* __restrict__ dst, int E,
                               const int* __restrict__ remap)
{
    int e = blockIdx.x * blockDim.x + threadIdx.x;
    if (e >= E) return;
    int d = dst[e];
    int p = g_off[d] + atomicAdd(&g_cur[d], 1);
    int s = src[e];
    g_esrc[p] = REMAP ? remap[s] : s;
}

// ---------------- mean aggregation: one warp per destination (4x edge unroll) ----------------
template <int LAYER>
__global__ void agg_kernel(const float4* __restrict__ hExt, int n_dst)
{
    const float4* __restrict__ h4 =
        (LAYER == 0) ? hExt : (LAYER == 1) ? (const float4*)g_h1 : (const float4*)g_h2;
    float4* __restrict__ agg4 =
        (LAYER == 0) ? g_agg0 : (LAYER == 1) ? g_agg1 : g_agg2;
    const int VPL = (LAYER == 0) ? 1 : 2;
    const int F4  = VPL * 32;

    int w = (blockIdx.x * blockDim.x + threadIdx.x) >> 5;
    int lane = threadIdx.x & 31;
    if (w >= n_dst) return;
    int s = g_off[w], e = g_off[w + 1];

    float4 acc[VPL];
#pragma unroll
    for (int v = 0; v < VPL; v++) acc[v] = make_float4(0.f, 0.f, 0.f, 0.f);

    int i = s;
    for (; i + 3 < e; i += 4) {           // 4x unroll for MLP
        int r0 = g_esrc[i], r1 = g_esrc[i + 1];
        int r2 = g_esrc[i + 2], r3 = g_esrc[i + 3];
#pragma unroll
        for (int v = 0; v < VPL; v++) {
            float4 x = h4[(size_t)r0 * F4 + v * 32 + lane];
            float4 y = h4[(size_t)r1 * F4 + v * 32 + lane];
            float4 z = h4[(size_t)r2 * F4 + v * 32 + lane];
            float4 u = h4[(size_t)r3 * F4 + v * 32 + lane];
            acc[v].x += (x.x + y.x) + (z.x + u.x);
            acc[v].y += (x.y + y.y) + (z.y + u.y);
            acc[v].z += (x.z + y.z) + (z.z + u.z);
            acc[v].w += (x.w + y.w) + (z.w + u.w);
        }
    }
    for (; i < e; i++) {
        int r0 = g_esrc[i];
#pragma unroll
        for (int v = 0; v < VPL; v++) {
            float4 x = h4[(size_t)r0 * F4 + v * 32 + lane];
            acc[v].x += x.x; acc[v].y += x.y; acc[v].z += x.z; acc[v].w += x.w;
        }
    }
    int cnt = e - s;
    float inv = 1.0f / (float)(cnt > 0 ? cnt : 1);
#pragma unroll
    for (int v = 0; v < VPL; v++) {
        agg4[(size_t)w * F4 + v * 32 + lane] =
            make_float4(acc[v].x * inv, acc[v].y * inv, acc[v].z * inv, acc[v].w * inv);
    }
}

// ---------------- weight prep (single merged kernel) ----------------
// fp32 [K][N] -> bf16 hi/lo [N][K], all four weight matrices in one launch.
__global__ void w2bf_all_kernel(const float* __restrict__ Ws0, const float* __restrict__ Wn0,
                                const float* __restrict__ Ws1, const float* __restrict__ Wn1)
{
    int i = blockIdx.x * blockDim.x + threadIdx.x;
    if (i >= 2 * FIN * FH + 2 * FH * FH) return;

    const float* W;
    __nv_bfloat16 *outH, *outL;
    int K, li;
    if (i < FIN * FH) {
        W = Ws0; outH = g_B0h; outL = g_B0l; K = FIN; li = i;
    } else if (i < 2 * FIN * FH) {
        W = Wn0; outH = g_B0h + FH * FIN; outL = g_B0l + FH * FIN; K = FIN; li = i - FIN * FH;
    } else if (i < 2 * FIN * FH + FH * FH) {
        W = Ws1; outH = g_B1h; outL = g_B1l; K = FH; li = i - 2 * FIN * FH;
    } else {
        W = Wn1; outH = g_B1h + FH * FH; outL = g_B1l + FH * FH; K = FH; li = i - 2 * FIN * FH - FH * FH;
    }
    int k = li / FH, n = li % FH;
    float x = W[li];
    __nv_bfloat16 h = __float2bfloat16(x);
    __nv_bfloat16 l = __float2bfloat16(x - __bfloat162float(h));
    outH[n * K + k] = h;
    outL[n * K + k] = l;
}

// ---------------- warp-MMA dual-operand GEMM (3xBF16 split) ----------------
// C[128,128-tile of 256] = relu( A1@B1 + A2@B2 + bias ), fp32 accumulators.
// LAYER 0: A1 = emb rows via inodes (K=128), A2 = g_agg0, C = g_h1
// LAYER 1: A1 = g_h1 (K=256),                A2 = g_agg1, C = g_h2
// 256 threads = 8 warps; warp (wm, wn) computes 32x64; KTILE=32 per SMEM pass.
#define KTILE 32

template <int LAYER>
__global__ void __launch_bounds__(256) mma_gemm_kernel(
    const float* __restrict__ A1ext, const int* __restrict__ inodes,
    const float* __restrict__ bias)
{
    __shared__ int s_rows[128];
    __shared__ __align__(1024) __nv_bfloat16 sAh[128 * KTILE];
    __shared__ __align__(1024) __nv_bfloat16 sAl[128 * KTILE];
    __shared__ __align__(1024) __nv_bfloat16 sBh[128 * KTILE];
    __shared__ __align__(1024) __nv_bfloat16 sBl[128 * KTILE];

    const int tid  = threadIdx.x;
    const int lane = tid & 31;
    const int wid  = tid >> 5;
    const int wm   = wid & 3;       // 4 M-warps
    const int wn   = wid >> 2;      // 2 N-warps

    const int KOP   = (LAYER == 0) ? FIN : FH;
    const int TPO   = KOP / KTILE;
    const float* __restrict__ A1 = (LAYER == 0) ? A1ext : (const float*)g_h1;
    const float* __restrict__ A2 = (LAYER == 0) ? (const float*)g_agg0 : (const float*)g_agg1;
    float* __restrict__ C        = (LAYER == 0) ? (float*)g_h1 : (float*)g_h2;
    const __nv_bfloat16* __restrict__ BHg = (LAYER == 0) ? g_B0h : g_B1h;
    const __nv_bfloat16* __restrict__ BLg = (LAYER == 0) ? g_B0l : g_B1l;

    const int mbase = blockIdx.x * 128;
    const int n0cta = blockIdx.y * 128;

    if (tid < 128) s_rows[tid] = (LAYER == 0) ? __ldg(&inodes[mbase + tid]) : (mbase + tid);
    __syncthreads();

    const uint32_t bAh = smem_u32(sAh), bAl = smem_u32(sAl);
    const uint32_t bBh = smem_u32(sBh), bBl = smem_u32(sBl);

    float d[2][8][4];
#pragma unroll
    for (int mi = 0; mi < 2; mi++)
#pragma unroll
        for (int ni = 0; ni < 8; ni++)
#pragma unroll
            for (int j = 0; j < 4; j++) d[mi][ni][j] = 0.f;

    for (int t = 0; t < 2 * TPO; t++) {
        const int op = t / TPO;
        const int k0 = (t % TPO) * KTILE;
        const float* __restrict__ Asrc = op ? A2 : A1;

        // ---- A tile: 128 rows x 32 k, fp32 -> bf16 hi/lo, SW64 SMEM ----
#pragma unroll
        for (int it = 0; it < 4; it++) {
            int fi  = it * 256 + tid;           // float4 idx 0..1023
            int row = fi >> 3;
            int k4  = (fi & 7) << 2;
            int arow = op ? (mbase + row) : s_rows[row];
            float4 v = *(const float4*)(Asrc + (size_t)arow * KOP + k0 + k4);
            __nv_bfloat16 h0 = __float2bfloat16(v.x), h1 = __float2bfloat16(v.y);
            __nv_bfloat16 h2 = __float2bfloat16(v.z), h3 = __float2bfloat16(v.w);
            __nv_bfloat16 l0 = __float2bfloat16(v.x - __bfloat162float(h0));
            __nv_bfloat16 l1 = __float2bfloat16(v.y - __bfloat162float(h1));
            __nv_bfloat16 l2 = __float2bfloat16(v.z - __bfloat162float(h2));
            __nv_bfloat16 l3 = __float2bfloat16(v.w - __bfloat162float(h3));
            uint32_t off = sw64((uint32_t)(row * 64 + k4 * 2));
            __nv_bfloat162* ph = (__nv_bfloat162*)((char*)sAh + off);
            __nv_bfloat162* pl = (__nv_bfloat162*)((char*)sAl + off);
            ph[0] = __nv_bfloat162(h0, h1); ph[1] = __nv_bfloat162(h2, h3);
            pl[0] = __nv_bfloat162(l0, l1); pl[1] = __nv_bfloat162(l2, l3);
        }
        // ---- B tile: 128 n-rows x 32 k, bf16 [N][KOP] global, SW64 SMEM ----
        const __nv_bfloat16* __restrict__ BH = BHg + (size_t)op * FH * KOP;
        const __nv_bfloat16* __restrict__ BL = BLg + (size_t)op * FH * KOP;
#pragma unroll
        for (int it = 0; it < 4; it++) {
            int ci = it * 256 + tid;            // 8B-chunk idx 0..1023
            int n  = ci >> 3;                   // 0..127
            int kc = (ci & 7) << 2;             // 0..28
            uint32_t off = sw64((uint32_t)(n * 64 + kc * 2));
            size_t gi = (size_t)(n0cta + n) * KOP + k0 + kc;
            *(uint64_t*)((char*)sBh + off) = *(const uint64_t*)(BH + gi);
            *(uint64_t*)((char*)sBl + off) = *(const uint64_t*)(BL + gi);
        }
        __syncthreads();

        // ---- compute: 2 k16-steps, 3 split terms each ----
#pragma unroll
        for (int k16 = 0; k16 < 2; k16++) {
            const int kb = k16 * 32;
            const uint32_t aoff0 = sw64((uint32_t)((wm * 32 + (lane & 15)) * 64 + kb + (lane >> 4) * 16));
            const uint32_t aoff1 = sw64((uint32_t)((wm * 32 + 16 + (lane & 15)) * 64 + kb + (lane >> 4) * 16));
            uint32_t ah[2][4], al[2][4], bh[8][2], bl[8][2];
            ldsm4(ah[0], bAh + aoff0);
            ldsm4(ah[1], bAh + aoff1);
            ldsm4(al[0], bAl + aoff0);
            ldsm4(al[1], bAl + aoff1);
#pragma unroll
            for (int ni = 0; ni < 8; ni++) {
                uint32_t boff = sw64((uint32_t)((wn * 64 + ni * 8 + (lane & 7)) * 64 + kb + ((lane >> 3) & 1) * 16));
                ldsm2(bh[ni], bBh + boff);
                ldsm2(bl[ni], bBl + boff);
            }
#pragma unroll
            for (int mi = 0; mi < 2; mi++)
#pragma unroll
                for (int ni = 0; ni < 8; ni++) {
                    mma_bf16(d[mi][ni], ah[mi], bh[ni]);   // hi*hi
                    mma_bf16(d[mi][ni], al[mi], bh[ni]);   // lo*hi
                    mma_bf16(d[mi][ni], ah[mi], bl[ni]);   // hi*lo
                }
        }
        __syncthreads();
    }

    // ---- epilogue: bias + relu, direct global stores ----
#pragma unroll
    for (int mi = 0; mi < 2; mi++) {
        int row0 = mbase + wm * 32 + mi * 16 + (lane >> 2);
#pragma unroll
        for (int ni = 0; ni < 8; ni++) {
            int col = n0cta + wn * 64 + ni * 8 + (lane & 3) * 2;
            float2 bv = *(const float2*)(bias + col);
            float2 v0, v1;
            v0.x = fmaxf(d[mi][ni][0] + bv.x, 0.f);
            v0.y = fmaxf(d[mi][ni][1] + bv.y, 0.f);
            v1.x = fmaxf(d[mi][ni][2] + bv.x, 0.f);
            v1.y = fmaxf(d[mi][ni][3] + bv.y, 0.f);
            *(float2*)(C + (size_t)row0 * FH + col)       = v0;
            *(float2*)(C + (size_t)(row0 + 8) * FH + col) = v1;
        }
    }
}

// ---------------- layer 2 (tiny, N=47) ----------------
__global__ void layer2_kernel(const float* __restrict__ Ws, const float* __restrict__ Wn,
                              const float* __restrict__ b, float* __restrict__ out)
{
    int m = blockIdx.x;
    int n = threadIdx.x;
    if (n >= NCLS) return;
    float acc = b[n];
    const float* hr = (const float*)g_h2   + (size_t)m * FH;
    const float* ar = (const float*)g_agg2 + (size_t)m * FH;
#pragma unroll 4
    for (int k = 0; k < FH; k++)
        acc += hr[k] * Ws[k * NCLS + n] + ar[k] * Wn[k * NCLS + n];
    out[m * NCLS + n] = acc;
}

// ---------------- orchestration (kernel launches ONLY — graph-capturable) ----------------
static inline void run_scan(int n)
{
    int nb = (n + 1023) / 1024;
    scan_partial_kernel<<<nb, 1024>>>(n);
    scan_bsums_kernel<<<1, 128>>>(nb);
    scan_addoff_kernel<<<nb, 1024>>>(n);
}

extern "C" void kernel_launch(void* const* d_in, const int* in_sizes, int n_in,
                              void* d_out, int out_size)
{
    (void)in_sizes; (void)n_in; (void)out_size;
    const float* emb         = (const float*)d_in[0];
    const int*   input_nodes = (const int*)  d_in[1];
    const int*   src0        = (const int*)  d_in[2];
    const int*   dst0        = (const int*)  d_in[3];
    const int*   src1        = (const int*)  d_in[4];
    const int*   dst1        = (const int*)  d_in[5];
    const int*   src2        = (const int*)  d_in[6];
    const int*   dst2        = (const int*)  d_in[7];
    const float* Ws0         = (const float*)d_in[8];
    const float* Wn0         = (const float*)d_in[9];
    const float* b0          = (const float*)d_in[10];
    const float* Ws1         = (const float*)d_in[11];
    const float* Wn1         = (const float*)d_in[12];
    const float* b1          = (const float*)d_in[13];
    const float* Ws2         = (const float*)d_in[14];
    const float* Wn2         = (const float*)d_in[15];
    const float* b2          = (const float*)d_in[16];
    float* out = (float*)d_out;

    const int TB = 256;

    // weight prep (bf16 hi/lo + transpose), single launch for all four matrices
    {
        int total = 2 * FIN * FH + 2 * FH * FH;
        w2bf_all_kernel<<<(total + TB - 1) / TB, TB>>>(Ws0, Wn0, Ws1, Wn1);
    }

    // ---- layer 0 ----
    zero2_kernel<<<(NDST0 + TB - 1) / TB, TB>>>(NDST0);
    hist_kernel<<<(NE0 + TB - 1) / TB, TB>>>(dst0, NE0);
    run_scan(NDST0);
    scatter_kernel<1><<<(NE0 + TB - 1) / TB, TB>>>(src0, dst0, NE0, input_nodes);
    agg_kernel<0><<<(NDST0 + 7) / 8, TB>>>((const float4*)emb, NDST0);
    {
        dim3 grid(NDST0 / 128, FH / 128);
        mma_gemm_kernel<0><<<grid, 256>>>(emb, input_nodes, b0);
    }

    // ---- layer 1 ----
    zero2_kernel<<<(NDST1 + TB - 1) / TB, TB>>>(NDST1);
    hist_kernel<<<(NE1 + TB - 1) / TB, TB>>>(dst1, NE1);
    run_scan(NDST1);
    scatter_kernel<0><<<(NE1 + TB - 1) / TB, TB>>>(src1, dst1, NE1, input_nodes);
    agg_kernel<1><<<(NDST1 + 7) / 8, TB>>>((const float4*)emb, NDST1);
    {
        dim3 grid(NDST1 / 128, FH / 128);
        mma_gemm_kernel<1><<<grid, 256>>>(emb, input_nodes, b1);
    }

    // ---- layer 2 ----
    zero2_kernel<<<(NDST2 + TB - 1) / TB, TB>>>(NDST2);
    hist_kernel<<<(NE2 + TB - 1) / TB, TB>>>(dst2, NE2);
    run_scan(NDST2);
    scatter_kernel<0><<<(NE2 + TB - 1) / TB, TB>>>(src2, dst2, NE2, input_nodes);
    agg_kernel<2><<<(NDST2 + 7) / 8, TB>>>((const float4*)emb, NDST2);
    layer2_kernel<<<NDST2, 64>>>(Ws2, Wn2, b2, out);
}